// round 10
// baseline (speedup 1.0000x reference)
#include <cuda_runtime.h>
#include <math.h>

#define L_DIM 128
#define D_DIM 64
#define M_DIM 256
#define TPB   768
#define TILE  96     // 24 warps x 4 rows
#define CPAD  68     // padded row stride for cen_p (conflict-free float4)

__device__ float g_cenT[D_DIM * M_DIM];   // cen transposed [d][m], original order
__device__ int   g_order[M_DIM];
__device__ int   g_cs[8], g_ce[8];

__global__ void cen_kernel(const float* __restrict__ cfeat,
                           const float* __restrict__ conf,
                           const float* __restrict__ W,
                           const float* __restrict__ bias)
{
    int m = blockIdx.x, d = threadIdx.x;
    const float* row = cfeat + m * L_DIM;
    float acc = bias[d];
#pragma unroll 8
    for (int k = 0; k < L_DIM; k++)
        acc = fmaf(row[k], W[k * D_DIM + d], acc);
    g_cenT[d * M_DIM + m] = conf[m] * acc;
}

// counting sort of centroids by batch id (ids are NOT sorted in the data)
__global__ void prep_order(const int* __restrict__ cen_c)
{
    __shared__ int cnt[8], base[8];
    const int tid = threadIdx.x;
    if (tid < 8) cnt[tid] = 0;
    __syncthreads();
    const int b = cen_c[4 * tid];
    atomicAdd(&cnt[b], 1);
    __syncthreads();
    if (tid == 0) {
        int a = 0;
        for (int bb = 0; bb < 8; bb++) {
            base[bb] = a; g_cs[bb] = a; a += cnt[bb]; g_ce[bb] = a;
        }
    }
    __syncthreads();
    g_order[atomicAdd(&base[b], 1)] = tid;
}

__global__ __launch_bounds__(TPB, 1)
void main_kernel(const int*   __restrict__ clu_c,
                 const int*   __restrict__ cen_c,
                 const float* __restrict__ feats,
                 const float* __restrict__ bias,
                 const float* __restrict__ Wg,
                 float*       __restrict__ out,
                 int N, int numTiles)
{
    extern __shared__ float sm[];
    float* W_s     = sm;                          // 8192
    float* cen_p   = W_s + L_DIM * D_DIM;         // 256*68 = 17408 (permuted, padded)
    float* b_s     = cen_p + M_DIM * CPAD;        // 64
    float* feats_s = b_s + D_DIM;                 // 96*128 = 12288
    float* clu_s   = feats_s + TILE * L_DIM;      // 96*64  = 6144
    float* vbuf    = clu_s + TILE * D_DIM;        // 24 warps * 256 = 6144
    int4*  cm4_s   = (int4*)(vbuf + 24 * M_DIM);  // 256 int4 (permuted)
    int*   ord_s   = (int*)(cm4_s + M_DIM);       // 256
    int*   cs_s    = ord_s + M_DIM;               // 8
    int*   ce_s    = cs_s + 8;                    // 8
    int*   rb_s    = ce_s + 8;                    // 96 each
    int*   rx_s    = rb_s + TILE;
    int*   ry_s    = rx_s + TILE;
    int*   rz_s    = ry_s + TILE;
    int*   rn2_s   = rz_s + TILE;

    const int tid  = threadIdx.x;
    const int warp = tid >> 5;
    const int lane = tid & 31;

    // ---- one-time staging ----
    if (tid < M_DIM) ord_s[tid] = g_order[tid];
    if (tid < 8) { cs_s[tid] = g_cs[tid]; ce_s[tid] = g_ce[tid]; }
    if (tid < D_DIM) b_s[tid] = bias[tid];
    for (int i = tid; i < L_DIM * D_DIM; i += TPB) W_s[i] = Wg[i];
    __syncthreads();   // ord_s ready
    // cen_p[j][d] = cen(original ord[j], d), padded stride CPAD
    for (int i = tid; i < M_DIM * D_DIM; i += TPB) {
        const int j = i >> 6, d = i & 63;
        cen_p[j * CPAD + d] = g_cenT[d * M_DIM + ord_s[j]];
    }
    if (tid < M_DIM) {
        int4 c = ((const int4*)cen_c)[ord_s[tid]];
        cm4_s[tid] = make_int4(c.y, c.z, c.w, c.y*c.y + c.z*c.z + c.w*c.w);
    }
    __syncthreads();

    for (int tile = blockIdx.x; tile < numTiles; tile += gridDim.x) {
        const int row0 = tile * TILE;
        const int nval = min(TILE, N - row0);

        // ---- load feats tile (zero-pad invalid rows) + row coords ----
        {
            const float4* fg = (const float4*)(feats + (long long)row0 * L_DIM);
            float4* fs = (float4*)feats_s;
            for (int i = tid; i < TILE * (L_DIM/4); i += TPB) {
                const int row = i >> 5;
                fs[i] = (row < nval) ? fg[i] : make_float4(0.f, 0.f, 0.f, 0.f);
            }
            if (tid < TILE) {
                if (tid < nval) {
                    int4 c = ((const int4*)clu_c)[row0 + tid];
                    rb_s[tid] = c.x; rx_s[tid] = c.y; ry_s[tid] = c.z; rz_s[tid] = c.w;
                    rn2_s[tid] = c.y*c.y + c.z*c.z + c.w*c.w;
                } else rb_s[tid] = -1;
            }
        }
        __syncthreads();

        // ---- Phase A: warp -> rows 4w..4w+3; lane -> cols 2lane,2lane+1 ----
        float sc0, sc1, sc2, sc3;
        {
            const float* f0 = feats_s + (4*warp) * L_DIM;
            const float* f1 = f0 + L_DIM;
            const float* f2 = f1 + L_DIM;
            const float* f3 = f2 + L_DIM;
            const float bx = b_s[2*lane], by = b_s[2*lane+1];
            float a0x=bx,a0y=by,a1x=bx,a1y=by,a2x=bx,a2y=by,a3x=bx,a3y=by;
#pragma unroll 2
            for (int k0 = 0; k0 < L_DIM; k0 += 4) {
                const float4 x0 = *(const float4*)(f0 + k0);
                const float4 x1 = *(const float4*)(f1 + k0);
                const float4 x2 = *(const float4*)(f2 + k0);
                const float4 x3 = *(const float4*)(f3 + k0);
                const float* p0 = (const float*)&x0;
                const float* p1 = (const float*)&x1;
                const float* p2 = (const float*)&x2;
                const float* p3 = (const float*)&x3;
#pragma unroll
                for (int kk = 0; kk < 4; kk++) {
                    const float2 w2 = *(const float2*)(W_s + (k0+kk)*D_DIM + 2*lane);
                    a0x = fmaf(p0[kk], w2.x, a0x); a0y = fmaf(p0[kk], w2.y, a0y);
                    a1x = fmaf(p1[kk], w2.x, a1x); a1y = fmaf(p1[kk], w2.y, a1y);
                    a2x = fmaf(p2[kk], w2.x, a2x); a2y = fmaf(p2[kk], w2.y, a2y);
                    a3x = fmaf(p3[kk], w2.x, a3x); a3y = fmaf(p3[kk], w2.y, a3y);
                }
            }
            float* c0 = clu_s + (4*warp)*D_DIM + 2*lane;
            *(float2*)(c0)             = make_float2(a0x, a0y);
            *(float2*)(c0 +   D_DIM)   = make_float2(a1x, a1y);
            *(float2*)(c0 + 2*D_DIM)   = make_float2(a2x, a2y);
            *(float2*)(c0 + 3*D_DIM)   = make_float2(a3x, a3y);

            float q0 = a0x*a0x + a0y*a0y;
            float q1 = a1x*a1x + a1y*a1y;
            float q2 = a2x*a2x + a2y*a2y;
            float q3 = a3x*a3x + a3y*a3y;
#pragma unroll
            for (int off = 16; off; off >>= 1) {
                q0 += __shfl_xor_sync(0xffffffffu, q0, off);
                q1 += __shfl_xor_sync(0xffffffffu, q1, off);
                q2 += __shfl_xor_sync(0xffffffffu, q2, off);
                q3 += __shfl_xor_sync(0xffffffffu, q3, off);
            }
            sc0 = 1.0f / fmaxf(sqrtf(q0), 1e-12f);
            sc1 = 1.0f / fmaxf(sqrtf(q1), 1e-12f);
            sc2 = 1.0f / fmaxf(sqrtf(q2), 1e-12f);
            sc3 = 1.0f / fmaxf(sqrtf(q3), 1e-12f);
        }
        __syncwarp();   // clu_s rows are warp-private

        // ---- Phase B: per row; full row built in per-warp smem buffer ----
        float* vb = vbuf + warp * M_DIM;
#pragma unroll 1
        for (int rr = 0; rr < 4; rr++) {
            const int r = 4*warp + rr;
            const int row = row0 + r;
            if (row >= N) continue;
            const int rb = rb_s[r];
            const int s = cs_s[rb], e = ce_s[rb];
            const int rx = rx_s[r], ry = ry_s[r], rz = rz_s[r], rn2 = rn2_s[r];
            const float* cr = clu_s + r * D_DIM;
            const float scale = rr == 0 ? sc0 : rr == 1 ? sc1 : rr == 2 ? sc2 : sc3;

            // zero the row buffer (conflict-free)
            {
                const float4 z = make_float4(0.f, 0.f, 0.f, 0.f);
                *(float4*)(vb + lane*4)       = z;
                *(float4*)(vb + 128 + lane*4) = z;
            }
            __syncwarp();

            float sumv = 0.f;
            if (e > s) {
                const int nc = (e - s + 31) >> 5;

                // pass 1: integer min of squared distance (no sqrt in loop)
                int best = 0x7fffffff;
#pragma unroll 1
                for (int c = 0; c < nc; c++) {
                    const int jj = s + (c << 5) + lane;
                    const int j = (jj < e) ? jj : s;
                    const int4 cm = cm4_s[j];
                    const int d2 = rn2 + cm.w - 2*(rx*cm.x + ry*cm.y + rz*cm.z);
                    if (jj < e) best = min(best, d2);
                }
#pragma unroll
                for (int off = 16; off; off >>= 1)
                    best = min(best, __shfl_xor_sync(0xffffffffu, best, off));
                const float dmin = fmaxf(sqrtf((float)best), 0.1f);  // = -max logit

                // pass 2: float4 dot + exp, scatter v*e into row buffer, sum
#pragma unroll 1
                for (int c = 0; c < nc; c++) {
                    const int jj = s + (c << 5) + lane;
                    const bool val = jj < e;
                    const int j = val ? jj : s;
                    const float* cpr = cen_p + j * CPAD;
                    float v0 = 0.f, v1 = 0.f, v2 = 0.f, v3 = 0.f;
#pragma unroll
                    for (int d = 0; d < D_DIM; d += 4) {
                        const float4 a  = *(const float4*)(cr  + d);   // broadcast
                        const float4 cc = *(const float4*)(cpr + d);   // conflict-free
                        v0 = fmaf(a.x, cc.x, v0);
                        v1 = fmaf(a.y, cc.y, v1);
                        v2 = fmaf(a.z, cc.z, v2);
                        v3 = fmaf(a.w, cc.w, v3);
                    }
                    const float v = (v0 + v1) + (v2 + v3);
                    const int4 cm = cm4_s[j];
                    const int d2 = rn2 + cm.w - 2*(rx*cm.x + ry*cm.y + rz*cm.z);
                    const float dist = fmaxf(sqrtf((float)d2), 0.1f);
                    const float ee = val ? __expf(dmin - dist) : 0.f;
                    if (val) vb[ord_s[jj]] = v * ee;
                    sumv += ee;
                }
#pragma unroll
                for (int off = 16; off; off >>= 1)
                    sumv += __shfl_xor_sync(0xffffffffu, sumv, off);
            }
            __syncwarp();

            // coalesced full-row write (empty batch -> zeros)
            const float rinv = (sumv > 0.f) ? (scale / sumv) : 0.f;
            float* orow = out + (long long)row * M_DIM;
            float4 o0 = *(const float4*)(vb + lane*4);
            float4 o1 = *(const float4*)(vb + 128 + lane*4);
            o0.x *= rinv; o0.y *= rinv; o0.z *= rinv; o0.w *= rinv;
            o1.x *= rinv; o1.y *= rinv; o1.z *= rinv; o1.w *= rinv;
            *(float4*)(orow + lane*4)       = o0;
            *(float4*)(orow + 128 + lane*4) = o1;
            __syncwarp();   // vb reuse for next row
        }
        __syncthreads();
    }
}

extern "C" void kernel_launch(void* const* d_in, const int* in_sizes, int n_in,
                              void* d_out, int out_size)
{
    const int*   clu_c = (const int*)  d_in[0];
    const int*   cen_c = (const int*)  d_in[1];
    const float* feats = (const float*)d_in[2];
    const float* cfeat = (const float*)d_in[3];
    const float* conf  = (const float*)d_in[4];
    const float* W     = (const float*)d_in[5];
    const float* bias  = (const float*)d_in[6];
    float* out = (float*)d_out;

    const int N = in_sizes[2] / L_DIM;
    const int numTiles = (N + TILE - 1) / TILE;

    // smem: floats 8192+17408+64+12288+6144+6144 = 50240
    //     + ints 1024+256+16+5*96 = 1776   -> 208064 B
    const size_t SMEM = (size_t)(50240 + 1776) * 4;

    prep_order<<<1, M_DIM>>>(cen_c);
    cen_kernel<<<M_DIM, D_DIM>>>(cfeat, conf, W, bias);

    cudaFuncSetAttribute(main_kernel,
                         cudaFuncAttributeMaxDynamicSharedMemorySize, (int)SMEM);
    main_kernel<<<148, TPB, SMEM>>>(clu_c, cen_c, feats, bias, W, out, N, numTiles);
}

// round 11
// speedup vs baseline: 2.5248x; 2.5248x over previous
#include <cuda_runtime.h>
#include <math.h>

#define L_DIM 128
#define D_DIM 64
#define M_DIM 256
#define TPB   768
#define TILE  96     // 24 warps x 4 rows

__device__ float g_cenT[D_DIM * M_DIM];   // cen transposed [d][m], original order
__device__ int   g_order[M_DIM];
__device__ int   g_cs[8], g_ce[8];

__global__ void cen_kernel(const float* __restrict__ cfeat,
                           const float* __restrict__ conf,
                           const float* __restrict__ W,
                           const float* __restrict__ bias)
{
    int m = blockIdx.x, d = threadIdx.x;
    const float* row = cfeat + m * L_DIM;
    float acc = bias[d];
#pragma unroll 8
    for (int k = 0; k < L_DIM; k++)
        acc = fmaf(row[k], W[k * D_DIM + d], acc);
    g_cenT[d * M_DIM + m] = conf[m] * acc;
}

// counting sort of centroids by batch id (ids are NOT sorted in the data)
__global__ void prep_order(const int* __restrict__ cen_c)
{
    __shared__ int cnt[8], base[8];
    const int tid = threadIdx.x;
    if (tid < 8) cnt[tid] = 0;
    __syncthreads();
    const int b = cen_c[4 * tid];
    atomicAdd(&cnt[b], 1);
    __syncthreads();
    if (tid == 0) {
        int a = 0;
        for (int bb = 0; bb < 8; bb++) {
            base[bb] = a; g_cs[bb] = a; a += cnt[bb]; g_ce[bb] = a;
        }
    }
    __syncthreads();
    g_order[atomicAdd(&base[b], 1)] = tid;
}

__global__ __launch_bounds__(TPB, 1)
void main_kernel(const int*   __restrict__ clu_c,
                 const int*   __restrict__ cen_c,
                 const float* __restrict__ feats,
                 const float* __restrict__ bias,
                 const float* __restrict__ Wg,
                 float*       __restrict__ out,
                 int N, int numTiles)
{
    extern __shared__ float sm[];
    float* W_s     = sm;                          // 8192
    float* cenT_s  = W_s + L_DIM * D_DIM;         // 16384: permuted, [d][m] layout
    float* b_s     = cenT_s + D_DIM * M_DIM;      // 64
    float* feats_s = b_s + D_DIM;                 // 96*128 = 12288
    float* clu_s   = feats_s + TILE * L_DIM;      // 96*64  = 6144
    float* vbuf    = clu_s + TILE * D_DIM;        // 24 warps * 256 = 6144
    int4*  cm4_s   = (int4*)(vbuf + 24 * M_DIM);  // 256 int4 (permuted)
    int*   ord_s   = (int*)(cm4_s + M_DIM);       // 256
    int*   cs_s    = ord_s + M_DIM;               // 8
    int*   ce_s    = cs_s + 8;                    // 8
    int*   rb_s    = ce_s + 8;                    // 96 each
    int*   rx_s    = rb_s + TILE;
    int*   ry_s    = rx_s + TILE;
    int*   rz_s    = ry_s + TILE;
    int*   rn2_s   = rz_s + TILE;

    const int tid  = threadIdx.x;
    const int warp = tid >> 5;
    const int lane = tid & 31;

    // ---- one-time staging ----
    if (tid < M_DIM) ord_s[tid] = g_order[tid];
    if (tid < 8) { cs_s[tid] = g_cs[tid]; ce_s[tid] = g_ce[tid]; }
    if (tid < D_DIM) b_s[tid] = bias[tid];
    for (int i = tid; i < L_DIM * D_DIM; i += TPB) W_s[i] = Wg[i];
    __syncthreads();   // ord_s ready
    for (int i = tid; i < D_DIM * M_DIM; i += TPB) {
        const int d = i >> 8, j = i & 255;
        cenT_s[i] = g_cenT[d * M_DIM + ord_s[j]];
    }
    if (tid < M_DIM) {
        int4 c = ((const int4*)cen_c)[ord_s[tid]];
        cm4_s[tid] = make_int4(c.y, c.z, c.w, c.y*c.y + c.z*c.z + c.w*c.w);
    }
    __syncthreads();

    for (int tile = blockIdx.x; tile < numTiles; tile += gridDim.x) {
        const int row0 = tile * TILE;
        const int nval = min(TILE, N - row0);

        // ---- load feats tile (zero-pad invalid rows) + row coords ----
        {
            const float4* fg = (const float4*)(feats + (long long)row0 * L_DIM);
            float4* fs = (float4*)feats_s;
            for (int i = tid; i < TILE * (L_DIM/4); i += TPB) {
                const int row = i >> 5;
                fs[i] = (row < nval) ? fg[i] : make_float4(0.f, 0.f, 0.f, 0.f);
            }
            if (tid < TILE) {
                if (tid < nval) {
                    int4 c = ((const int4*)clu_c)[row0 + tid];
                    rb_s[tid] = c.x; rx_s[tid] = c.y; ry_s[tid] = c.z; rz_s[tid] = c.w;
                    rn2_s[tid] = c.y*c.y + c.z*c.z + c.w*c.w;
                } else rb_s[tid] = -1;
            }
        }
        __syncthreads();

        // ---- Phase A: warp -> rows 4w..4w+3; lane -> cols 2lane,2lane+1 ----
        float sc0, sc1, sc2, sc3;
        {
            const float* f0 = feats_s + (4*warp) * L_DIM;
            const float* f1 = f0 + L_DIM;
            const float* f2 = f1 + L_DIM;
            const float* f3 = f2 + L_DIM;
            const float bx = b_s[2*lane], by = b_s[2*lane+1];
            float a0x=bx,a0y=by,a1x=bx,a1y=by,a2x=bx,a2y=by,a3x=bx,a3y=by;
#pragma unroll 2
            for (int k0 = 0; k0 < L_DIM; k0 += 4) {
                const float4 x0 = *(const float4*)(f0 + k0);
                const float4 x1 = *(const float4*)(f1 + k0);
                const float4 x2 = *(const float4*)(f2 + k0);
                const float4 x3 = *(const float4*)(f3 + k0);
                const float* p0 = (const float*)&x0;
                const float* p1 = (const float*)&x1;
                const float* p2 = (const float*)&x2;
                const float* p3 = (const float*)&x3;
#pragma unroll
                for (int kk = 0; kk < 4; kk++) {
                    const float2 w2 = *(const float2*)(W_s + (k0+kk)*D_DIM + 2*lane);
                    a0x = fmaf(p0[kk], w2.x, a0x); a0y = fmaf(p0[kk], w2.y, a0y);
                    a1x = fmaf(p1[kk], w2.x, a1x); a1y = fmaf(p1[kk], w2.y, a1y);
                    a2x = fmaf(p2[kk], w2.x, a2x); a2y = fmaf(p2[kk], w2.y, a2y);
                    a3x = fmaf(p3[kk], w2.x, a3x); a3y = fmaf(p3[kk], w2.y, a3y);
                }
            }
            float* c0 = clu_s + (4*warp)*D_DIM + 2*lane;
            *(float2*)(c0)             = make_float2(a0x, a0y);
            *(float2*)(c0 +   D_DIM)   = make_float2(a1x, a1y);
            *(float2*)(c0 + 2*D_DIM)   = make_float2(a2x, a2y);
            *(float2*)(c0 + 3*D_DIM)   = make_float2(a3x, a3y);

            float q0 = a0x*a0x + a0y*a0y;
            float q1 = a1x*a1x + a1y*a1y;
            float q2 = a2x*a2x + a2y*a2y;
            float q3 = a3x*a3x + a3y*a3y;
#pragma unroll
            for (int off = 16; off; off >>= 1) {
                q0 += __shfl_xor_sync(0xffffffffu, q0, off);
                q1 += __shfl_xor_sync(0xffffffffu, q1, off);
                q2 += __shfl_xor_sync(0xffffffffu, q2, off);
                q3 += __shfl_xor_sync(0xffffffffu, q3, off);
            }
            sc0 = 1.0f / fmaxf(sqrtf(q0), 1e-12f);
            sc1 = 1.0f / fmaxf(sqrtf(q1), 1e-12f);
            sc2 = 1.0f / fmaxf(sqrtf(q2), 1e-12f);
            sc3 = 1.0f / fmaxf(sqrtf(q3), 1e-12f);
        }
        __syncwarp();   // clu_s rows are warp-private

        // ---- Phase B: per row; full row built in per-warp smem buffer ----
        float* vb = vbuf + warp * M_DIM;
#pragma unroll 1
        for (int rr = 0; rr < 4; rr++) {
            const int r = 4*warp + rr;
            const int row = row0 + r;
            if (row >= N) continue;
            const int rb = rb_s[r];
            const int s = cs_s[rb], e = ce_s[rb];
            const int rx = rx_s[r], ry = ry_s[r], rz = rz_s[r], rn2 = rn2_s[r];
            const float* cr = clu_s + r * D_DIM;
            const float scale = rr == 0 ? sc0 : rr == 1 ? sc1 : rr == 2 ? sc2 : sc3;

            // zero the row buffer (conflict-free)
            {
                const float4 z = make_float4(0.f, 0.f, 0.f, 0.f);
                *(float4*)(vb + lane*4)       = z;
                *(float4*)(vb + 128 + lane*4) = z;
            }
            __syncwarp();

            float sumv = 0.f;
            if (e > s) {
                const int nc = (e - s + 31) >> 5;

                // pass 1: pure-integer min of squared distance (no MUFU in loop)
                int best = 0x7fffffff;
#pragma unroll 1
                for (int c = 0; c < nc; c++) {
                    const int jj = s + (c << 5) + lane;
                    const int j = (jj < e) ? jj : s;
                    const int4 cm = cm4_s[j];
                    const int d2 = rn2 + cm.w - 2*(rx*cm.x + ry*cm.y + rz*cm.z);
                    if (jj < e) best = min(best, d2);
                }
#pragma unroll
                for (int off = 16; off; off >>= 1)
                    best = min(best, __shfl_xor_sync(0xffffffffu, best, off));
                const float dmin = fmaxf(sqrtf((float)best), 0.1f);  // = -max logit

                // pass 2: dot + exp, scatter v*e into row buffer, sum
#pragma unroll 1
                for (int c = 0; c < nc; c++) {
                    const int jj = s + (c << 5) + lane;
                    const bool val = jj < e;
                    const int j = val ? jj : s;
                    float v0 = 0.f, v1 = 0.f, v2 = 0.f, v3 = 0.f;
#pragma unroll 4
                    for (int d = 0; d < D_DIM; d += 4) {
                        const float4 a = *(const float4*)(cr + d);
                        v0 = fmaf(a.x, cenT_s[ d   *M_DIM + j], v0);
                        v1 = fmaf(a.y, cenT_s[(d+1)*M_DIM + j], v1);
                        v2 = fmaf(a.z, cenT_s[(d+2)*M_DIM + j], v2);
                        v3 = fmaf(a.w, cenT_s[(d+3)*M_DIM + j], v3);
                    }
                    const float v = (v0 + v1) + (v2 + v3);
                    const int4 cm = cm4_s[j];
                    const int d2 = rn2 + cm.w - 2*(rx*cm.x + ry*cm.y + rz*cm.z);
                    const float dist = fmaxf(sqrtf((float)d2), 0.1f);
                    const float ee = val ? __expf(dmin - dist) : 0.f;
                    if (val) vb[ord_s[jj]] = v * ee;
                    sumv += ee;
                }
#pragma unroll
                for (int off = 16; off; off >>= 1)
                    sumv += __shfl_xor_sync(0xffffffffu, sumv, off);
            }
            __syncwarp();

            // coalesced full-row write (empty batch -> zeros)
            const float rinv = (sumv > 0.f) ? (scale / sumv) : 0.f;
            float* orow = out + (long long)row * M_DIM;
            float4 o0 = *(const float4*)(vb + lane*4);
            float4 o1 = *(const float4*)(vb + 128 + lane*4);
            o0.x *= rinv; o0.y *= rinv; o0.z *= rinv; o0.w *= rinv;
            o1.x *= rinv; o1.y *= rinv; o1.z *= rinv; o1.w *= rinv;
            *(float4*)(orow + lane*4)       = o0;
            *(float4*)(orow + 128 + lane*4) = o1;
            __syncwarp();   // vb reuse for next row
        }
        __syncthreads();
    }
}

extern "C" void kernel_launch(void* const* d_in, const int* in_sizes, int n_in,
                              void* d_out, int out_size)
{
    const int*   clu_c = (const int*)  d_in[0];
    const int*   cen_c = (const int*)  d_in[1];
    const float* feats = (const float*)d_in[2];
    const float* cfeat = (const float*)d_in[3];
    const float* conf  = (const float*)d_in[4];
    const float* W     = (const float*)d_in[5];
    const float* bias  = (const float*)d_in[6];
    float* out = (float*)d_out;

    const int N = in_sizes[2] / L_DIM;
    const int numTiles = (N + TILE - 1) / TILE;

    // smem: floats 8192+16384+64+12288+6144+6144 = 49216
    //     + ints 256*4+256+16+5*96 = 1776   -> 203968 B
    const size_t SMEM = (size_t)(49216 + 1776) * 4;

    prep_order<<<1, M_DIM>>>(cen_c);
    cen_kernel<<<M_DIM, D_DIM>>>(cfeat, conf, W, bias);

    cudaFuncSetAttribute(main_kernel,
                         cudaFuncAttributeMaxDynamicSharedMemorySize, (int)SMEM);
    main_kernel<<<148, TPB, SMEM>>>(clu_c, cen_c, feats, bias, W, out, N, numTiles);
}

// round 12
// speedup vs baseline: 2.9300x; 1.1605x over previous
#include <cuda_runtime.h>
#include <math.h>

#define L_DIM 128
#define D_DIM 64
#define M_DIM 256
#define TPB   768
#define NWARP 24

__device__ float g_cenT[D_DIM * M_DIM];   // cen transposed [d][m], original order
__device__ int   g_order[M_DIM];
__device__ int   g_cs[8], g_ce[8];

__global__ void cen_kernel(const float* __restrict__ cfeat,
                           const float* __restrict__ conf,
                           const float* __restrict__ W,
                           const float* __restrict__ bias)
{
    int m = blockIdx.x, d = threadIdx.x;
    const float* row = cfeat + m * L_DIM;
    float acc = bias[d];
#pragma unroll 8
    for (int k = 0; k < L_DIM; k++)
        acc = fmaf(row[k], W[k * D_DIM + d], acc);
    g_cenT[d * M_DIM + m] = conf[m] * acc;
}

// counting sort of centroids by batch id (ids are NOT sorted in the data)
__global__ void prep_order(const int* __restrict__ cen_c)
{
    __shared__ int cnt[8], base[8];
    const int tid = threadIdx.x;
    if (tid < 8) cnt[tid] = 0;
    __syncthreads();
    const int b = cen_c[4 * tid];
    atomicAdd(&cnt[b], 1);
    __syncthreads();
    if (tid == 0) {
        int a = 0;
        for (int bb = 0; bb < 8; bb++) {
            base[bb] = a; g_cs[bb] = a; a += cnt[bb]; g_ce[bb] = a;
        }
    }
    __syncthreads();
    g_order[atomicAdd(&base[b], 1)] = tid;
}

__global__ __launch_bounds__(TPB, 1)
void main_kernel(const int*   __restrict__ clu_c,
                 const int*   __restrict__ cen_c,
                 const float* __restrict__ feats,
                 const float* __restrict__ bias,
                 const float* __restrict__ Wg,
                 float*       __restrict__ out,
                 int N, int numGroups)
{
    extern __shared__ float sm[];
    float* W_s     = sm;                           // 8192
    float* cenT_s  = W_s + L_DIM * D_DIM;          // 16384: permuted, [d][m]
    float* b_s     = cenT_s + D_DIM * M_DIM;       // 64
    float* feats_s = b_s + D_DIM;                  // 24 warps * 4*128 = 12288
    float* clu_s   = feats_s + NWARP * 4 * L_DIM;  // 24 * 4*64 = 6144
    float* vbuf    = clu_s + NWARP * 4 * D_DIM;    // 24 * 256 = 6144
    int4*  cm4_s   = (int4*)(vbuf + NWARP * M_DIM);// 256 int4 (permuted)
    int*   ord_s   = (int*)(cm4_s + M_DIM);        // 256
    int*   cs_s    = ord_s + M_DIM;                // 8
    int*   ce_s    = cs_s + 8;                     // 8
    int*   rmeta   = ce_s + 8;                     // 24 warps * 20 ints

    const int tid  = threadIdx.x;
    const int warp = tid >> 5;
    const int lane = tid & 31;

    // ---- one-time staging (the ONLY block barrier region) ----
    if (tid < M_DIM) ord_s[tid] = g_order[tid];
    if (tid < 8) { cs_s[tid] = g_cs[tid]; ce_s[tid] = g_ce[tid]; }
    if (tid < D_DIM) b_s[tid] = bias[tid];
    for (int i = tid; i < L_DIM * D_DIM; i += TPB) W_s[i] = Wg[i];
    __syncthreads();   // ord_s ready
    for (int i = tid; i < D_DIM * M_DIM; i += TPB) {
        const int d = i >> 8, j = i & 255;
        cenT_s[i] = g_cenT[d * M_DIM + ord_s[j]];
    }
    if (tid < M_DIM) {
        int4 c = ((const int4*)cen_c)[ord_s[tid]];
        cm4_s[tid] = make_int4(c.y, c.z, c.w, c.y*c.y + c.z*c.z + c.w*c.w);
    }
    __syncthreads();

    // per-warp private slices
    float* fw = feats_s + warp * (4 * L_DIM);
    float* cw = clu_s   + warp * (4 * D_DIM);
    float* vb = vbuf    + warp * M_DIM;
    int*   mw = rmeta   + warp * 20;      // rb[4], rx[4], ry[4], rz[4], rn2[4]

    // ---- warp-autonomous group loop: NO block barriers ----
    for (int g = blockIdx.x * NWARP + warp; g < numGroups;
         g += gridDim.x * NWARP) {
        const int row0 = g * 4;

        // load own 4 feats rows (coalesced LDG.128) + own coords
        float4 fv0, fv1, fv2, fv3;
        {
            const float4 z = make_float4(0.f, 0.f, 0.f, 0.f);
            const long long r0 = row0;
            fv0 = (r0   < N) ? *(const float4*)(feats + (r0  )*L_DIM + lane*4) : z;
            fv1 = (r0+1 < N) ? *(const float4*)(feats + (r0+1)*L_DIM + lane*4) : z;
            fv2 = (r0+2 < N) ? *(const float4*)(feats + (r0+2)*L_DIM + lane*4) : z;
            fv3 = (r0+3 < N) ? *(const float4*)(feats + (r0+3)*L_DIM + lane*4) : z;
        }
        if (lane < 4) {
            const long long r = row0 + lane;
            if (r < N) {
                int4 c = ((const int4*)clu_c)[r];
                mw[lane]      = c.x;
                mw[4 + lane]  = c.y;
                mw[8 + lane]  = c.z;
                mw[12 + lane] = c.w;
                mw[16 + lane] = c.y*c.y + c.z*c.z + c.w*c.w;
            } else mw[lane] = -1;
        }
        ((float4*)(fw          ))[lane] = fv0;
        ((float4*)(fw +   L_DIM))[lane] = fv1;
        ((float4*)(fw + 2*L_DIM))[lane] = fv2;
        ((float4*)(fw + 3*L_DIM))[lane] = fv3;
        __syncwarp();

        // ---- Phase A: 4 rows; lane -> cols 2lane,2lane+1 ----
        float sc0, sc1, sc2, sc3;
        {
            const float* f0 = fw;
            const float* f1 = fw + L_DIM;
            const float* f2 = fw + 2*L_DIM;
            const float* f3 = fw + 3*L_DIM;
            const float bx = b_s[2*lane], by = b_s[2*lane+1];
            float a0x=bx,a0y=by,a1x=bx,a1y=by,a2x=bx,a2y=by,a3x=bx,a3y=by;
#pragma unroll 2
            for (int k0 = 0; k0 < L_DIM; k0 += 4) {
                const float4 x0 = *(const float4*)(f0 + k0);
                const float4 x1 = *(const float4*)(f1 + k0);
                const float4 x2 = *(const float4*)(f2 + k0);
                const float4 x3 = *(const float4*)(f3 + k0);
                const float* p0 = (const float*)&x0;
                const float* p1 = (const float*)&x1;
                const float* p2 = (const float*)&x2;
                const float* p3 = (const float*)&x3;
#pragma unroll
                for (int kk = 0; kk < 4; kk++) {
                    const float2 w2 = *(const float2*)(W_s + (k0+kk)*D_DIM + 2*lane);
                    a0x = fmaf(p0[kk], w2.x, a0x); a0y = fmaf(p0[kk], w2.y, a0y);
                    a1x = fmaf(p1[kk], w2.x, a1x); a1y = fmaf(p1[kk], w2.y, a1y);
                    a2x = fmaf(p2[kk], w2.x, a2x); a2y = fmaf(p2[kk], w2.y, a2y);
                    a3x = fmaf(p3[kk], w2.x, a3x); a3y = fmaf(p3[kk], w2.y, a3y);
                }
            }
            float* c0 = cw + 2*lane;
            *(float2*)(c0)             = make_float2(a0x, a0y);
            *(float2*)(c0 +   D_DIM)   = make_float2(a1x, a1y);
            *(float2*)(c0 + 2*D_DIM)   = make_float2(a2x, a2y);
            *(float2*)(c0 + 3*D_DIM)   = make_float2(a3x, a3y);

            float q0 = a0x*a0x + a0y*a0y;
            float q1 = a1x*a1x + a1y*a1y;
            float q2 = a2x*a2x + a2y*a2y;
            float q3 = a3x*a3x + a3y*a3y;
#pragma unroll
            for (int off = 16; off; off >>= 1) {
                q0 += __shfl_xor_sync(0xffffffffu, q0, off);
                q1 += __shfl_xor_sync(0xffffffffu, q1, off);
                q2 += __shfl_xor_sync(0xffffffffu, q2, off);
                q3 += __shfl_xor_sync(0xffffffffu, q3, off);
            }
            sc0 = 1.0f / fmaxf(sqrtf(q0), 1e-12f);
            sc1 = 1.0f / fmaxf(sqrtf(q1), 1e-12f);
            sc2 = 1.0f / fmaxf(sqrtf(q2), 1e-12f);
            sc3 = 1.0f / fmaxf(sqrtf(q3), 1e-12f);
        }
        __syncwarp();

        // ---- Phase B: per row; full row built in per-warp smem buffer ----
#pragma unroll 1
        for (int rr = 0; rr < 4; rr++) {
            const int row = row0 + rr;
            if (row >= N) continue;
            const int rb = mw[rr];
            const int s = cs_s[rb], e = ce_s[rb];
            const int rx = mw[4+rr], ry = mw[8+rr], rz = mw[12+rr], rn2 = mw[16+rr];
            const float* cr = cw + rr * D_DIM;
            const float scale = rr == 0 ? sc0 : rr == 1 ? sc1 : rr == 2 ? sc2 : sc3;

            // zero the row buffer
            {
                const float4 z = make_float4(0.f, 0.f, 0.f, 0.f);
                *(float4*)(vb + lane*4)       = z;
                *(float4*)(vb + 128 + lane*4) = z;
            }
            __syncwarp();

            float sumv = 0.f;
            if (rb >= 0 && e > s) {
                const int nc = (e - s + 31) >> 5;

                // pass 1: pure-integer min of squared distance
                int best = 0x7fffffff;
#pragma unroll 1
                for (int c = 0; c < nc; c++) {
                    const int jj = s + (c << 5) + lane;
                    const int j = (jj < e) ? jj : s;
                    const int4 cm = cm4_s[j];
                    const int d2 = rn2 + cm.w - 2*(rx*cm.x + ry*cm.y + rz*cm.z);
                    if (jj < e) best = min(best, d2);
                }
#pragma unroll
                for (int off = 16; off; off >>= 1)
                    best = min(best, __shfl_xor_sync(0xffffffffu, best, off));
                const float dmin = fmaxf(sqrtf((float)best), 0.1f);  // = -max logit

                // pass 2: dot + exp, scatter v*e into row buffer, sum
#pragma unroll 1
                for (int c = 0; c < nc; c++) {
                    const int jj = s + (c << 5) + lane;
                    const bool val = jj < e;
                    const int j = val ? jj : s;
                    float v0 = 0.f, v1 = 0.f, v2 = 0.f, v3 = 0.f;
#pragma unroll 4
                    for (int d = 0; d < D_DIM; d += 4) {
                        const float4 a = *(const float4*)(cr + d);
                        v0 = fmaf(a.x, cenT_s[ d   *M_DIM + j], v0);
                        v1 = fmaf(a.y, cenT_s[(d+1)*M_DIM + j], v1);
                        v2 = fmaf(a.z, cenT_s[(d+2)*M_DIM + j], v2);
                        v3 = fmaf(a.w, cenT_s[(d+3)*M_DIM + j], v3);
                    }
                    const float v = (v0 + v1) + (v2 + v3);
                    const int4 cm = cm4_s[j];
                    const int d2 = rn2 + cm.w - 2*(rx*cm.x + ry*cm.y + rz*cm.z);
                    const float dist = fmaxf(sqrtf((float)d2), 0.1f);
                    const float ee = val ? __expf(dmin - dist) : 0.f;
                    if (val) vb[ord_s[jj]] = v * ee;
                    sumv += ee;
                }
#pragma unroll
                for (int off = 16; off; off >>= 1)
                    sumv += __shfl_xor_sync(0xffffffffu, sumv, off);
            }
            __syncwarp();

            // coalesced full-row write (empty batch -> zeros)
            const float rinv = (sumv > 0.f) ? (scale / sumv) : 0.f;
            float* orow = out + (long long)row * M_DIM;
            float4 o0 = *(const float4*)(vb + lane*4);
            float4 o1 = *(const float4*)(vb + 128 + lane*4);
            o0.x *= rinv; o0.y *= rinv; o0.z *= rinv; o0.w *= rinv;
            o1.x *= rinv; o1.y *= rinv; o1.z *= rinv; o1.w *= rinv;
            *(float4*)(orow + lane*4)       = o0;
            *(float4*)(orow + 128 + lane*4) = o1;
            __syncwarp();   // vb reuse for next row
        }
        // no block barrier: everything in the loop is warp-private
    }
}

extern "C" void kernel_launch(void* const* d_in, const int* in_sizes, int n_in,
                              void* d_out, int out_size)
{
    const int*   clu_c = (const int*)  d_in[0];
    const int*   cen_c = (const int*)  d_in[1];
    const float* feats = (const float*)d_in[2];
    const float* cfeat = (const float*)d_in[3];
    const float* conf  = (const float*)d_in[4];
    const float* W     = (const float*)d_in[5];
    const float* bias  = (const float*)d_in[6];
    float* out = (float*)d_out;

    const int N = in_sizes[2] / L_DIM;
    const int numGroups = (N + 3) / 4;

    // smem: floats 8192+16384+64+12288+6144+6144 = 49216
    //     + ints 1024+256+16+480 = 1776   -> 203968 B
    const size_t SMEM = (size_t)(49216 + 1776) * 4;

    prep_order<<<1, M_DIM>>>(cen_c);
    cen_kernel<<<M_DIM, D_DIM>>>(cfeat, conf, W, bias);

    cudaFuncSetAttribute(main_kernel,
                         cudaFuncAttributeMaxDynamicSharedMemorySize, (int)SMEM);
    main_kernel<<<148, TPB, SMEM>>>(clu_c, cen_c, feats, bias, W, out, N, numGroups);
}